// round 12
// baseline (speedup 1.0000x reference)
#include <cuda_runtime.h>
#include <cuda_bf16.h>
#include <cmath>

#define T_  200
#define B_  256
#define M_  (T_ * B_)      // 51200 rows

__device__ float g_hs[M_ * 50];      // [T,B,H]

// ---------------- helpers ----------------
__device__ __forceinline__ unsigned long long fma2(unsigned long long a,
                                                   unsigned long long b,
                                                   unsigned long long c) {
    unsigned long long d;
    asm("fma.rn.f32x2 %0, %1, %2, %3;" : "=l"(d) : "l"(a), "l"(b), "l"(c));
    return d;
}
__device__ __forceinline__ unsigned long long add2(unsigned long long a,
                                                   unsigned long long b) {
    unsigned long long d;
    asm("add.rn.f32x2 %0, %1, %2;" : "=l"(d) : "l"(a), "l"(b));
    return d;
}
__device__ __forceinline__ float2 u2f(unsigned long long v) {
    float2 r;
    asm("mov.b64 {%0, %1}, %2;" : "=f"(r.x), "=f"(r.y) : "l"(v));
    return r;
}
__device__ __forceinline__ unsigned smem_u32(const void* p) {
    return (unsigned)__cvta_generic_to_shared(p);
}
__device__ __forceinline__ void cp16(unsigned dst, const void* src) {
    asm volatile("cp.async.cg.shared.global [%0], [%1], 16;" :: "r"(dst), "l"(src));
}
__device__ __forceinline__ float frcp(float x) {
    float r; asm("rcp.approx.f32 %0, %1;" : "=f"(r) : "f"(x)); return r;
}
__device__ __forceinline__ float sigm(float x) {
    return frcp(1.f + __expf(-x));
}

__device__ __forceinline__ void mma_bf16(float* c, const unsigned* a,
                                         unsigned b0, unsigned b1) {
    asm volatile(
        "mma.sync.aligned.m16n8k16.row.col.f32.bf16.bf16.f32 "
        "{%0,%1,%2,%3}, {%4,%5,%6,%7}, {%8,%9}, {%0,%1,%2,%3};"
        : "+f"(c[0]), "+f"(c[1]), "+f"(c[2]), "+f"(c[3])
        : "r"(a[0]), "r"(a[1]), "r"(a[2]), "r"(a[3]), "r"(b0), "r"(b1));
}
__device__ __forceinline__ void ldsm_x4(unsigned* r, unsigned addr) {
    asm volatile(
        "ldmatrix.sync.aligned.m8n8.x4.shared.b16 {%0,%1,%2,%3}, [%4];"
        : "=r"(r[0]), "=r"(r[1]), "=r"(r[2]), "=r"(r[3]) : "r"(addr));
}
__device__ __forceinline__ void bf16_split(float x, __nv_bfloat16& h,
                                           __nv_bfloat16& l) {
    h = __float2bfloat16_rn(x);
    l = __float2bfloat16_rn(x - __bfloat162float(h));
}
__device__ __forceinline__ unsigned pack_bf2(__nv_bfloat16 lo16, __nv_bfloat16 hi16) {
    __nv_bfloat162 v(lo16, hi16);
    return *reinterpret_cast<unsigned*>(&v);
}

// ---------------------------------------------------------------------------
// Fused kernel: LSTM recurrence (R5 consumer) + in-CTA x_proj production.
// 128 CTAs x 512 threads, 2 groups of 256; group g owns batch b = blk*2+g.
// Rotated role index v (g=1 -> (n+64)&255):
//   v < 200 : gate threads (R5 dot);  v < 50 : also cell update + g_hs store
//   v in [224,256): PRODUCER warp (full contiguous warp in both groups).
// Producer, per 16-step block, builds x_proj rows t0..t0+15 for batch b via
// bf16 3-term-split mma (m16 x n200 x k128) into a double-buffered smem ring.
// Slices (1/step): 0 token LDG prefetch; 1 cp.async gather; 2-3 fp32->bf16
// split planes; 4-15 MMA n-tiles (2,2,...,2,3). Block 0 built in prologue.
// W_ih hi/lo planes staged once per CTA (R10 layouts, proven).
// ---------------------------------------------------------------------------
#define GRP_W   10624
#define XR_OFF  0       // 2*16*200 = 6400 words
#define AS_OFF  6400    // 16*128   = 2048
#define AH_OFF  8448    // 16*68    = 1088
#define AL_OFF  9536    // 16*68    = 1088
#define SM_WORDS (25800 + 2 * GRP_W)   // 47048 words = 188,192 B

__global__ __launch_bounds__(512, 1) void k_fused(
    const int*   __restrict__ tokens,
    const float* __restrict__ emb,
    const float* __restrict__ Wih,
    const float* __restrict__ Whh,
    const float* __restrict__ bih,
    const float* __restrict__ bhh)
{
    extern __shared__ __align__(16) float sm[];
    unsigned* BHI  = reinterpret_cast<unsigned*>(sm);          // 12800
    unsigned* BLO  = reinterpret_cast<unsigned*>(sm + 12800);  // 12800
    float*    bsum = sm + 25600;                               // 200

    __shared__ __align__(16) float h_s[2][52];
    __shared__ float gates_s[2][200];

    const int tid = threadIdx.x;
    const int g   = tid >> 8;
    const int n   = tid & 255;
    const int v   = g ? ((n + 64) & 255) : n;
    const int b   = blockIdx.x * 2 + g;

    float* grp  = sm + 25800 + g * GRP_W;
    float* xr   = grp + XR_OFF;
    float* asta = grp + AS_OFF;
    unsigned* AHI = reinterpret_cast<unsigned*>(grp + AH_OFF);
    unsigned* ALO = reinterpret_cast<unsigned*>(grp + AL_OFF);

    const bool gate = (v < 200);
    const bool prod = (v >= 224);
    const int  lane = n & 31;

    // ---- stage W_ih as hi/lo bf16 frag planes (R10 layout) ----
    for (int i = tid; i < 12800; i += 512) {
        const int nn = i >> 6;
        const int kp = i & 63;
        const int s  = kp >> 3;
        const int hh = (kp >> 2) & 1;
        const int cc = kp & 3;
        const int nt = nn >> 3;
        const int gg = nn & 7;
        const int dst = (((s * 25 + nt) * 32) + gg * 4 + cc) * 2 + hh;
        const float2 vv = *reinterpret_cast<const float2*>(Wih + nn * 128 + 2 * kp);
        __nv_bfloat16 h0, l0, h1, l1;
        bf16_split(vv.x, h0, l0);
        bf16_split(vv.y, h1, l1);
        BHI[dst] = pack_bf2(h0, h1);
        BLO[dst] = pack_bf2(l0, l1);
    }
    if (tid < 200) bsum[tid] = bih[tid] + bhh[tid];
    if (v < 52)    h_s[g][v] = 0.f;

    unsigned long long w2[25];
    if (gate) {
        const float2* wr = reinterpret_cast<const float2*>(Whh + v * 50);
#pragma unroll
        for (int q = 0; q < 25; q++)
            w2[q] = *reinterpret_cast<const unsigned long long*>(&wr[q]);
    }
    __syncthreads();

    // producer constants
    const unsigned ahi_b = smem_u32(AHI);
    const unsigned alo_b = smem_u32(ALO);
    const int r_ln = lane >> 2;
    const int c_ln = lane & 3;
    const unsigned aoff_l =
        (unsigned)(((lane & 7) + ((lane >> 3) & 1) * 8) * 68 + (lane >> 4) * 4);
    int tokp = 0;   // prefetched token (lanes 0-15)

    // one n-tile of the production MMA into ring buffer nb
#define PROD_TILE(nt, nb)                                                     \
    do {                                                                      \
        float acc[4] = {0.f, 0.f, 0.f, 0.f};                                  \
        _Pragma("unroll")                                                     \
        for (int s = 0; s < 8; s++) {                                         \
            unsigned ah[4], al[4];                                            \
            ldsm_x4(ah, ahi_b + (aoff_l + (unsigned)(s * 8)) * 4u);           \
            ldsm_x4(al, alo_b + (aoff_l + (unsigned)(s * 8)) * 4u);           \
            const int bw = ((s * 25 + (nt)) * 32 + lane) * 2;                 \
            const unsigned long long bh =                                     \
                *reinterpret_cast<const unsigned long long*>(&BHI[bw]);       \
            const unsigned long long bl =                                     \
                *reinterpret_cast<const unsigned long long*>(&BLO[bw]);       \
            const unsigned bh0 = (unsigned)bh, bh1 = (unsigned)(bh >> 32);    \
            const unsigned bl0 = (unsigned)bl, bl1 = (unsigned)(bl >> 32);    \
            mma_bf16(acc, ah, bh0, bh1);                                      \
            mma_bf16(acc, ah, bl0, bl1);                                      \
            mma_bf16(acc, al, bh0, bh1);                                      \
        }                                                                     \
        const int col = (nt) * 8 + 2 * c_ln;                                  \
        float* dst = xr + (nb) * 3200;                                        \
        float2 o0, o1;                                                        \
        o0.x = acc[0] + bsum[col];                                            \
        o0.y = acc[1] + bsum[col + 1];                                        \
        o1.x = acc[2] + bsum[col];                                            \
        o1.y = acc[3] + bsum[col + 1];                                        \
        *reinterpret_cast<float2*>(&dst[r_ln * 200 + col]) = o0;              \
        *reinterpret_cast<float2*>(&dst[(r_ln + 8) * 200 + col]) = o1;        \
    } while (0)

    // ---- prologue: produce block 0 into ring buffer 0 (serial) ----
    if (prod) {
        if (lane < 16) tokp = tokens[lane * 256 + b];
#pragma unroll
        for (int i = 0; i < 16; i++) {
            const int tk = __shfl_sync(0xffffffffu, tokp, i);
            cp16(smem_u32(&asta[i * 128 + lane * 4]),
                 emb + (size_t)tk * 128 + lane * 4);
        }
        asm volatile("cp.async.commit_group;");
        asm volatile("cp.async.wait_group 0;");
        __syncwarp();
#pragma unroll
        for (int jj = 0; jj < 32; jj++) {
            const int w  = jj * 32 + lane;
            const int r  = w >> 6;
            const int kp = w & 63;
            const float2 vv =
                *reinterpret_cast<const float2*>(&asta[r * 128 + 2 * kp]);
            __nv_bfloat16 h0, l0, h1, l1;
            bf16_split(vv.x, h0, l0);
            bf16_split(vv.y, h1, l1);
            AHI[r * 68 + kp] = pack_bf2(h0, h1);
            ALO[r * 68 + kp] = pack_bf2(l0, l1);
        }
        __syncwarp();
        for (int nt = 0; nt < 25; nt++) PROD_TILE(nt, 0);
    }
    __syncthreads();

    float c = 0.f;

    for (int t = 0; t < T_; t++) {
        const int slot = t & 15;
        const int bb   = (t >> 4) & 1;
        const int t0   = ((t >> 4) + 1) * 16;   // block being produced

        // ---- phase 1: gate dots + producer slice ----
        if (gate) {
            const float xp = xr[bb * 3200 + slot * 200 + v];
            const unsigned long long* h2 =
                reinterpret_cast<const unsigned long long*>(h_s[g]);
            unsigned long long a0 = 0ull, a1 = 0ull, a2 = 0ull, a3 = 0ull;
#pragma unroll
            for (int q = 0; q < 24; q += 4) {
                a0 = fma2(h2[q],     w2[q],     a0);
                a1 = fma2(h2[q + 1], w2[q + 1], a1);
                a2 = fma2(h2[q + 2], w2[q + 2], a2);
                a3 = fma2(h2[q + 3], w2[q + 3], a3);
            }
            a0 = fma2(h2[24], w2[24], a0);
            a0 = add2(a0, a1);
            a2 = add2(a2, a3);
            a0 = add2(a0, a2);
            const float2 s = u2f(a0);
            gates_s[g][v] = xp + s.x + s.y;
        } else if (prod && t0 < T_) {
            const int nb = bb ^ 1;
            if (slot == 0) {
                if (lane < 16) {
                    const int ts = t0 + lane;
                    tokp = (ts < T_) ? tokens[ts * 256 + b] : 0;
                }
            } else if (slot == 1) {
#pragma unroll
                for (int i = 0; i < 16; i++) {
                    const int tk = __shfl_sync(0xffffffffu, tokp, i);
                    cp16(smem_u32(&asta[i * 128 + lane * 4]),
                         emb + (size_t)tk * 128 + lane * 4);
                }
                asm volatile("cp.async.commit_group;");
            } else if (slot == 2 || slot == 3) {
                if (slot == 2)
                    asm volatile("cp.async.wait_group 0;");
#pragma unroll
                for (int jj = 0; jj < 16; jj++) {
                    const int w  = (slot - 2) * 512 + jj * 32 + lane;
                    const int r  = w >> 6;
                    const int kp = w & 63;
                    const float2 vv = *reinterpret_cast<const float2*>(
                        &asta[r * 128 + 2 * kp]);
                    __nv_bfloat16 h0, l0, h1, l1;
                    bf16_split(vv.x, h0, l0);
                    bf16_split(vv.y, h1, l1);
                    AHI[r * 68 + kp] = pack_bf2(h0, h1);
                    ALO[r * 68 + kp] = pack_bf2(l0, l1);
                }
            } else {
                const int nt0 = (slot - 4) * 2;
                PROD_TILE(nt0, nb);
                PROD_TILE(nt0 + 1, nb);
                if (slot == 15) PROD_TILE(24, nb);
            }
        }
        asm volatile("bar.sync %0, 256;" :: "r"(g + 1) : "memory");

        // ---- phase 2: cell update ----
        if (v < 50) {
            const float iv = gates_s[g][v];
            const float fv = gates_s[g][v + 50];
            const float gv = gates_s[g][v + 100];
            const float ov = gates_s[g][v + 150];
            const float si = sigm(iv);
            const float sf = sigm(fv);
            const float so = sigm(ov);
            const float tg = fmaf(2.f, sigm(2.f * gv), -1.f);
            c = fmaf(sf, c, si * tg);
            const float tc = fmaf(2.f, sigm(2.f * c), -1.f);
            const float hn = so * tc;
            h_s[g][v] = hn;
            g_hs[(size_t)(t * B_ + b) * 50 + v] = hn;
        }
        asm volatile("bar.sync %0, 256;" :: "r"(g + 1) : "memory");
    }
#undef PROD_TILE
}

// ---------------------------------------------------------------------------
// K3: head. out[r,:] = relu(h_r @ W1^T + b1) @ W2^T + b2 (flat 51200 rows)
// ---------------------------------------------------------------------------
__global__ __launch_bounds__(256) void k3_head(
    const float* __restrict__ W1, const float* __restrict__ b1,
    const float* __restrict__ W2, const float* __restrict__ b2,
    float* __restrict__ out)
{
    __shared__ float sW1[16 * 50];
    __shared__ float sW2[9 * 16];
    __shared__ float sb1[16];
    __shared__ float sb2[9];

    const int tid = threadIdx.x;
    for (int i = tid; i < 800; i += 256) sW1[i] = W1[i];
    if (tid < 144) sW2[tid] = W2[tid];
    if (tid < 16)  sb1[tid] = b1[tid];
    if (tid < 9)   sb2[tid] = b2[tid];
    __syncthreads();

    const int r = blockIdx.x * 256 + tid;
    const float* __restrict__ hrow = &g_hs[(size_t)r * 50];

    float hv[50];
#pragma unroll
    for (int k = 0; k < 50; k++) hv[k] = hrow[k];

    float z[16];
#pragma unroll
    for (int jj = 0; jj < 16; jj++) {
        float a = sb1[jj];
#pragma unroll
        for (int k = 0; k < 50; k++) a = fmaf(hv[k], sW1[jj * 50 + k], a);
        z[jj] = fmaxf(a, 0.f);
    }
#pragma unroll
    for (int pp = 0; pp < 9; pp++) {
        float o = sb2[pp];
#pragma unroll
        for (int jj = 0; jj < 16; jj++) o = fmaf(z[jj], sW2[pp * 16 + jj], o);
        out[r * 9 + pp] = o;
    }
}

// ---------------------------------------------------------------------------
extern "C" void kernel_launch(void* const* d_in, const int* in_sizes, int n_in,
                              void* d_out, int out_size)
{
    const int*   tokens = (const int*)  d_in[0];
    const float* emb    = (const float*)d_in[1];
    const float* Wih    = (const float*)d_in[2];
    const float* Whh    = (const float*)d_in[3];
    const float* bih    = (const float*)d_in[4];
    const float* bhh    = (const float*)d_in[5];
    const float* W1     = (const float*)d_in[6];
    const float* b1     = (const float*)d_in[7];
    const float* W2     = (const float*)d_in[8];
    const float* b2     = (const float*)d_in[9];
    float* out = (float*)d_out;

    const int smem = SM_WORDS * 4;   // 188,192 B
    cudaFuncSetAttribute(k_fused, cudaFuncAttributeMaxDynamicSharedMemorySize,
                         smem);

    k_fused <<<B_ / 2, 512, smem>>>(tokens, emb, Wih, Whh, bih, bhh);
    k3_head <<<M_ / 256, 256>>>(W1, b1, W2, b2, out);
}

// round 13
// speedup vs baseline: 1.3208x; 1.3208x over previous
#include <cuda_runtime.h>
#include <cuda_bf16.h>
#include <cmath>

#define T_  200
#define B_  256
#define M_  (T_ * B_)      // 51200 rows

__device__ float g_xproj[M_ * 200];  // [T,B,4H] flat row r = t*256+b
__device__ float g_hs[M_ * 50];      // [T,B,H]

// ---------------- helpers ----------------
__device__ __forceinline__ unsigned long long fma2(unsigned long long a,
                                                   unsigned long long b,
                                                   unsigned long long c) {
    unsigned long long d;
    asm("fma.rn.f32x2 %0, %1, %2, %3;" : "=l"(d) : "l"(a), "l"(b), "l"(c));
    return d;
}
__device__ __forceinline__ unsigned long long add2(unsigned long long a,
                                                   unsigned long long b) {
    unsigned long long d;
    asm("add.rn.f32x2 %0, %1, %2;" : "=l"(d) : "l"(a), "l"(b));
    return d;
}
__device__ __forceinline__ float2 u2f(unsigned long long v) {
    float2 r;
    asm("mov.b64 {%0, %1}, %2;" : "=f"(r.x), "=f"(r.y) : "l"(v));
    return r;
}
__device__ __forceinline__ unsigned smem_u32(const void* p) {
    return (unsigned)__cvta_generic_to_shared(p);
}
__device__ __forceinline__ void cp16(unsigned dst, const void* src) {
    asm volatile("cp.async.cg.shared.global [%0], [%1], 16;" :: "r"(dst), "l"(src));
}
__device__ __forceinline__ float frcp(float x) {
    float r; asm("rcp.approx.f32 %0, %1;" : "=f"(r) : "f"(x)); return r;
}
__device__ __forceinline__ float sigm(float x) {
    return frcp(1.f + __expf(-x));
}

__device__ __forceinline__ void mma_bf16(float* c, const unsigned* a,
                                         unsigned b0, unsigned b1) {
    asm volatile(
        "mma.sync.aligned.m16n8k16.row.col.f32.bf16.bf16.f32 "
        "{%0,%1,%2,%3}, {%4,%5,%6,%7}, {%8,%9}, {%0,%1,%2,%3};"
        : "+f"(c[0]), "+f"(c[1]), "+f"(c[2]), "+f"(c[3])
        : "r"(a[0]), "r"(a[1]), "r"(a[2]), "r"(a[3]), "r"(b0), "r"(b1));
}
__device__ __forceinline__ void ldsm_x4(unsigned* r, unsigned addr) {
    asm volatile(
        "ldmatrix.sync.aligned.m8n8.x4.shared.b16 {%0,%1,%2,%3}, [%4];"
        : "=r"(r[0]), "=r"(r[1]), "=r"(r[2]), "=r"(r[3]) : "r"(addr));
}
__device__ __forceinline__ void bf16_split(float x, __nv_bfloat16& h,
                                           __nv_bfloat16& l) {
    h = __float2bfloat16_rn(x);
    l = __float2bfloat16_rn(x - __bfloat162float(h));
}
__device__ __forceinline__ unsigned pack_bf2(__nv_bfloat16 lo16, __nv_bfloat16 hi16) {
    __nv_bfloat162 v(lo16, hi16);
    return *reinterpret_cast<unsigned*>(&v);
}

// ---------------------------------------------------------------------------
// K1 (tensor, v2): x_proj = gather(emb, tokens) @ Wih^T + (bih+bhh)
// 148 CTAs x 512 threads (16 warps/SM, 2x R7). Tile m64 x n200 x k128,
// tiles strided: tile = cta, cta+148, ... (800 tiles).
// Warps: wm = wid>>3 (m32 half), ng = wid&7 (n-group; sizes 4,3,3,...,3).
// Gather: 8 threads/row, direct LDG.128 -> bf16 hi/lo split -> STS (no ASTA).
// smem words: BHI[12800] BLO[12800] AHI[4352] ALO[4352] bsum[200] = 34504
// ---------------------------------------------------------------------------
#define K1_SMEM_WORDS 34504   // 138,016 bytes

__global__ __launch_bounds__(512, 1) void k1_mma(
    const int*   __restrict__ tokens,
    const float* __restrict__ emb,
    const float* __restrict__ Wih,
    const float* __restrict__ bih,
    const float* __restrict__ bhh)
{
    extern __shared__ __align__(16) float sm[];
    unsigned* BHI  = reinterpret_cast<unsigned*>(sm);
    unsigned* BLO  = reinterpret_cast<unsigned*>(sm + 12800);
    unsigned* AHI  = reinterpret_cast<unsigned*>(sm + 25600);
    unsigned* ALO  = reinterpret_cast<unsigned*>(sm + 29952);
    float*    bsum = sm + 34304;

    const int tid  = threadIdx.x;
    const int lane = tid & 31;
    const int wid  = tid >> 5;        // 0..15
    const int wm   = wid >> 3;        // 0..1  (m32 half)
    const int ng   = wid & 7;         // 0..7  (n-group)
    const int ntb  = (ng == 0) ? 0 : (4 + 3 * (ng - 1));
    const int ncnt = (ng == 0) ? 4 : 3;

    const int r_ln = lane >> 2;
    const int c_ln = lane & 3;

    const int lrow  = (lane & 7) + ((lane >> 3) & 1) * 8;
    const int khalf = lane >> 4;
    int aoff[2];
#pragma unroll
    for (int f = 0; f < 2; f++)
        aoff[f] = (wm * 32 + f * 16 + lrow) * 68 + khalf * 4;
    const unsigned ahi_b = smem_u32(AHI);
    const unsigned alo_b = smem_u32(ALO);

    // stage Wih as hi/lo bf16 frag planes (h-paired layout, R10)
    for (int i = tid; i < 12800; i += 512) {
        const int nn = i >> 6;
        const int kp = i & 63;
        const int s  = kp >> 3;
        const int hh = (kp >> 2) & 1;
        const int cc = kp & 3;
        const int nt = nn >> 3;
        const int gg = nn & 7;
        const int dst = (((s * 25 + nt) * 32) + gg * 4 + cc) * 2 + hh;
        const float2 v = *reinterpret_cast<const float2*>(Wih + nn * 128 + 2 * kp);
        __nv_bfloat16 h0, l0, h1, l1;
        bf16_split(v.x, h0, l0);
        bf16_split(v.y, h1, l1);
        BHI[dst] = pack_bf2(h0, h1);
        BLO[dst] = pack_bf2(l0, l1);
    }
    if (tid < 200) bsum[tid] = bih[tid] + bhh[tid];

    const int grow = tid >> 3;   // gather: row within tile (0..63)
    const int gsub = tid & 7;    // 16-float chunk within row

    for (int tile = blockIdx.x; tile < 800; tile += 148) {
        const int row0 = tile * 64;

        // ---- gather + convert (direct LDG, no staging) ----
        {
            const int tok = tokens[row0 + grow];
            const float4* src = reinterpret_cast<const float4*>(
                emb + (size_t)tok * 128 + gsub * 16);
            const float4 v0 = src[0], v1 = src[1], v2 = src[2], v3 = src[3];
            const float xsrc[16] = {v0.x, v0.y, v0.z, v0.w, v1.x, v1.y, v1.z, v1.w,
                                    v2.x, v2.y, v2.z, v2.w, v3.x, v3.y, v3.z, v3.w};
            unsigned hw[8], lw[8];
#pragma unroll
            for (int p = 0; p < 8; p++) {
                __nv_bfloat16 h0, l0, h1, l1;
                bf16_split(xsrc[2 * p],     h0, l0);
                bf16_split(xsrc[2 * p + 1], h1, l1);
                hw[p] = pack_bf2(h0, h1);
                lw[p] = pack_bf2(l0, l1);
            }
            const int wbase = grow * 68 + gsub * 8;
            *reinterpret_cast<uint4*>(&AHI[wbase]) =
                make_uint4(hw[0], hw[1], hw[2], hw[3]);
            *reinterpret_cast<uint4*>(&AHI[wbase + 4]) =
                make_uint4(hw[4], hw[5], hw[6], hw[7]);
            *reinterpret_cast<uint4*>(&ALO[wbase]) =
                make_uint4(lw[0], lw[1], lw[2], lw[3]);
            *reinterpret_cast<uint4*>(&ALO[wbase + 4]) =
                make_uint4(lw[4], lw[5], lw[6], lw[7]);
        }
        __syncthreads();

        // ---- MMA ----
        float acc[4][2][4];
#pragma unroll
        for (int nt = 0; nt < 4; nt++)
#pragma unroll
            for (int f = 0; f < 2; f++)
#pragma unroll
                for (int e = 0; e < 4; e++) acc[nt][f][e] = 0.f;

#pragma unroll
        for (int s = 0; s < 8; s++) {
            unsigned ah[2][4], al[2][4];
#pragma unroll
            for (int f = 0; f < 2; f++) {
                ldsm_x4(ah[f], ahi_b + (unsigned)(aoff[f] + s * 8) * 4u);
                ldsm_x4(al[f], alo_b + (unsigned)(aoff[f] + s * 8) * 4u);
            }
#pragma unroll
            for (int nt = 0; nt < 4; nt++) {
                if (nt < ncnt) {
                    const int bw = (((s * 25 + ntb + nt) * 32) + lane) * 2;
                    const unsigned long long bh =
                        *reinterpret_cast<const unsigned long long*>(&BHI[bw]);
                    const unsigned long long bl =
                        *reinterpret_cast<const unsigned long long*>(&BLO[bw]);
                    const unsigned bh0 = (unsigned)bh, bh1 = (unsigned)(bh >> 32);
                    const unsigned bl0 = (unsigned)bl, bl1 = (unsigned)(bl >> 32);
#pragma unroll
                    for (int f = 0; f < 2; f++) {
                        mma_bf16(acc[nt][f], ah[f], bh0, bh1);
                        mma_bf16(acc[nt][f], ah[f], bl0, bl1);
                        mma_bf16(acc[nt][f], al[f], bh0, bh1);
                    }
                }
            }
        }

        // ---- epilogue ----
#pragma unroll
        for (int nt = 0; nt < 4; nt++) {
            if (nt < ncnt) {
                const int col = (ntb + nt) * 8 + 2 * c_ln;
                const float bx = bsum[col];
                const float by = bsum[col + 1];
#pragma unroll
                for (int f = 0; f < 2; f++) {
                    const int row = row0 + wm * 32 + f * 16 + r_ln;
                    float2 o0, o1;
                    o0.x = acc[nt][f][0] + bx;
                    o0.y = acc[nt][f][1] + by;
                    o1.x = acc[nt][f][2] + bx;
                    o1.y = acc[nt][f][3] + by;
                    *reinterpret_cast<float2*>(
                        &g_xproj[(size_t)row * 200 + col]) = o0;
                    *reinterpret_cast<float2*>(
                        &g_xproj[(size_t)(row + 8) * 200 + col]) = o1;
                }
            }
        }
        __syncthreads();
    }
}

// ---------------------------------------------------------------------------
// K2: LSTM recurrence (R5 exact: rotated SMSP roles, 8-deep cp.async ring)
// ---------------------------------------------------------------------------
#define S_ 8

__global__ __launch_bounds__(512, 1) void k2_lstm(const float* __restrict__ Whh)
{
    __shared__ __align__(16) float h_s[2][52];
    __shared__ float gates_s[2][200];
    __shared__ __align__(16) float xs[2][S_][200];

    const int tid = threadIdx.x;
    const int g   = tid >> 8;
    const int n   = tid & 255;
    const int v   = g ? ((n + 64) & 255) : n;   // rotated role index
    const int b   = blockIdx.x * 2 + g;

    const bool gate   = (v < 200);
    const bool loader = (v < 50);

    unsigned long long w2[25];
    if (gate) {
        const float2* wr = reinterpret_cast<const float2*>(Whh + v * 50);
#pragma unroll
        for (int q = 0; q < 25; q++)
            w2[q] = *reinterpret_cast<const unsigned long long*>(&wr[q]);
    }
    if (v < 52) h_s[g][v] = 0.f;

    if (loader) {
#pragma unroll
        for (int s = 0; s < S_ - 1; s++) {
            cp16(smem_u32(&xs[g][s][v * 4]),
                 g_xproj + ((size_t)(s * B_ + b) * 200) + v * 4);
            asm volatile("cp.async.commit_group;");
        }
        asm volatile("cp.async.wait_group %0;" :: "n"(S_ - 3));
    }
    __syncthreads();

    float c = 0.f;

    for (int t = 0; t < T_; t++) {
        const int slot = t & (S_ - 1);

        if (loader) {
            const int ts = t + S_ - 1;
            if (ts < T_)
                cp16(smem_u32(&xs[g][ts & (S_ - 1)][v * 4]),
                     g_xproj + ((size_t)(ts * B_ + b) * 200) + v * 4);
            asm volatile("cp.async.commit_group;");
        }

        if (gate) {
            const float xp = xs[g][slot][v];
            const unsigned long long* h2 =
                reinterpret_cast<const unsigned long long*>(h_s[g]);
            unsigned long long a0 = 0ull, a1 = 0ull, a2 = 0ull, a3 = 0ull;
#pragma unroll
            for (int q = 0; q < 24; q += 4) {
                a0 = fma2(h2[q],     w2[q],     a0);
                a1 = fma2(h2[q + 1], w2[q + 1], a1);
                a2 = fma2(h2[q + 2], w2[q + 2], a2);
                a3 = fma2(h2[q + 3], w2[q + 3], a3);
            }
            a0 = fma2(h2[24], w2[24], a0);
            a0 = add2(a0, a1);
            a2 = add2(a2, a3);
            a0 = add2(a0, a2);
            const float2 s = u2f(a0);
            gates_s[g][v] = xp + s.x + s.y;
        }
        if (loader)
            asm volatile("cp.async.wait_group %0;" :: "n"(S_ - 3));
        asm volatile("bar.sync %0, 256;" :: "r"(g + 1) : "memory");

        if (v < 50) {
            const float iv = gates_s[g][v];
            const float fv = gates_s[g][v + 50];
            const float gv = gates_s[g][v + 100];
            const float ov = gates_s[g][v + 150];
            const float si = sigm(iv);
            const float sf = sigm(fv);
            const float so = sigm(ov);
            const float tg = fmaf(2.f, sigm(2.f * gv), -1.f);
            c = fmaf(sf, c, si * tg);
            const float tc = fmaf(2.f, sigm(2.f * c), -1.f);
            const float hn = so * tc;
            h_s[g][v] = hn;
            g_hs[(size_t)(t * B_ + b) * 50 + v] = hn;
        }
        asm volatile("bar.sync %0, 256;" :: "r"(g + 1) : "memory");
    }
}

// ---------------------------------------------------------------------------
// K3 (v2): head with coalesced smem staging of the 256x50 h-block.
// ---------------------------------------------------------------------------
#define K3_SMEM_WORDS (12800 + 800 + 144 + 16 + 9)   // 55,076 bytes

__global__ __launch_bounds__(256) void k3_head(
    const float* __restrict__ W1, const float* __restrict__ b1,
    const float* __restrict__ W2, const float* __restrict__ b2,
    float* __restrict__ out)
{
    extern __shared__ __align__(16) float k3sm[];
    float* sh  = k3sm;             // 12800: 256 rows x 50
    float* sW1 = k3sm + 12800;     // 800
    float* sW2 = k3sm + 13600;     // 144
    float* sb1 = k3sm + 13744;     // 16
    float* sb2 = k3sm + 13760;     // 9

    const int tid = threadIdx.x;

    // coalesced stage of this CTA's h rows (contiguous 51200B)
    {
        const float4* src = reinterpret_cast<const float4*>(
            g_hs + (size_t)blockIdx.x * 12800);
        float4* dst = reinterpret_cast<float4*>(sh);
        for (int i = tid; i < 3200; i += 256) dst[i] = src[i];
    }
    for (int i = tid; i < 800; i += 256) sW1[i] = W1[i];
    if (tid < 144) sW2[tid] = W2[tid];
    if (tid < 16)  sb1[tid] = b1[tid];
    if (tid < 9)   sb2[tid] = b2[tid];
    __syncthreads();

    const int r = blockIdx.x * 256 + tid;
    const float* hrow = &sh[tid * 50];

    float z[16];
#pragma unroll
    for (int jj = 0; jj < 16; jj++) {
        float a = sb1[jj];
#pragma unroll
        for (int k = 0; k < 50; k++) a = fmaf(hrow[k], sW1[jj * 50 + k], a);
        z[jj] = fmaxf(a, 0.f);
    }
#pragma unroll
    for (int pp = 0; pp < 9; pp++) {
        float o = sb2[pp];
#pragma unroll
        for (int jj = 0; jj < 16; jj++) o = fmaf(z[jj], sW2[pp * 16 + jj], o);
        out[r * 9 + pp] = o;
    }
}

// ---------------------------------------------------------------------------
extern "C" void kernel_launch(void* const* d_in, const int* in_sizes, int n_in,
                              void* d_out, int out_size)
{
    const int*   tokens = (const int*)  d_in[0];
    const float* emb    = (const float*)d_in[1];
    const float* Wih    = (const float*)d_in[2];
    const float* Whh    = (const float*)d_in[3];
    const float* bih    = (const float*)d_in[4];
    const float* bhh    = (const float*)d_in[5];
    const float* W1     = (const float*)d_in[6];
    const float* b1     = (const float*)d_in[7];
    const float* W2     = (const float*)d_in[8];
    const float* b2     = (const float*)d_in[9];
    float* out = (float*)d_out;

    const int k1_smem = K1_SMEM_WORDS * 4;   // 138,016 B
    cudaFuncSetAttribute(k1_mma, cudaFuncAttributeMaxDynamicSharedMemorySize,
                         k1_smem);
    const int k3_smem = K3_SMEM_WORDS * 4;   // 55,076 B
    cudaFuncSetAttribute(k3_head, cudaFuncAttributeMaxDynamicSharedMemorySize,
                         k3_smem);

    k1_mma  <<<148, 512, k1_smem>>>(tokens, emb, Wih, bih, bhh);
    k2_lstm <<<B_ / 2, 512>>>(Whh);
    k3_head <<<M_ / 256, 256, k3_smem>>>(W1, b1, W2, b2, out);
}

// round 14
// speedup vs baseline: 1.3649x; 1.0334x over previous
#include <cuda_runtime.h>
#include <cuda_bf16.h>
#include <cmath>

#define T_  200
#define B_  256
#define M_  (T_ * B_)      // 51200 rows

__device__ float g_xproj[M_ * 200];  // [T,B,4H] flat row r = t*256+b
__device__ float g_hs[M_ * 50];      // [T,B,H]

// ---------------- helpers ----------------
__device__ __forceinline__ unsigned long long fma2(unsigned long long a,
                                                   unsigned long long b,
                                                   unsigned long long c) {
    unsigned long long d;
    asm("fma.rn.f32x2 %0, %1, %2, %3;" : "=l"(d) : "l"(a), "l"(b), "l"(c));
    return d;
}
__device__ __forceinline__ unsigned long long add2(unsigned long long a,
                                                   unsigned long long b) {
    unsigned long long d;
    asm("add.rn.f32x2 %0, %1, %2;" : "=l"(d) : "l"(a), "l"(b));
    return d;
}
__device__ __forceinline__ float2 u2f(unsigned long long v) {
    float2 r;
    asm("mov.b64 {%0, %1}, %2;" : "=f"(r.x), "=f"(r.y) : "l"(v));
    return r;
}
__device__ __forceinline__ unsigned smem_u32(const void* p) {
    return (unsigned)__cvta_generic_to_shared(p);
}
__device__ __forceinline__ void cp16(unsigned dst, const void* src) {
    asm volatile("cp.async.cg.shared.global [%0], [%1], 16;" :: "r"(dst), "l"(src));
}
__device__ __forceinline__ float frcp(float x) {
    float r; asm("rcp.approx.f32 %0, %1;" : "=f"(r) : "f"(x)); return r;
}
__device__ __forceinline__ float sigm(float x) {
    return frcp(1.f + __expf(-x));
}

__device__ __forceinline__ void mma_bf16(float* c, const unsigned* a,
                                         unsigned b0, unsigned b1) {
    asm volatile(
        "mma.sync.aligned.m16n8k16.row.col.f32.bf16.bf16.f32 "
        "{%0,%1,%2,%3}, {%4,%5,%6,%7}, {%8,%9}, {%0,%1,%2,%3};"
        : "+f"(c[0]), "+f"(c[1]), "+f"(c[2]), "+f"(c[3])
        : "r"(a[0]), "r"(a[1]), "r"(a[2]), "r"(a[3]), "r"(b0), "r"(b1));
}
__device__ __forceinline__ void ldsm_x4(unsigned* r, unsigned addr) {
    asm volatile(
        "ldmatrix.sync.aligned.m8n8.x4.shared.b16 {%0,%1,%2,%3}, [%4];"
        : "=r"(r[0]), "=r"(r[1]), "=r"(r[2]), "=r"(r[3]) : "r"(addr));
}
__device__ __forceinline__ void bf16_split(float x, __nv_bfloat16& h,
                                           __nv_bfloat16& l) {
    h = __float2bfloat16_rn(x);
    l = __float2bfloat16_rn(x - __bfloat162float(h));
}
__device__ __forceinline__ unsigned pack_bf2(__nv_bfloat16 lo16, __nv_bfloat16 hi16) {
    __nv_bfloat16 x2[2] = {lo16, hi16};
    return *reinterpret_cast<unsigned*>(x2);
}

// ---------------------------------------------------------------------------
// K1 (tensor, v2 + token prefetch): x_proj = gather @ Wih^T + (bih+bhh)
// 148 CTAs x 512 threads. Tile m64 x n200 x k128, tiles strided by 148.
// ---------------------------------------------------------------------------
#define K1_SMEM_WORDS 34504   // 138,016 bytes

__global__ __launch_bounds__(512, 1) void k1_mma(
    const int*   __restrict__ tokens,
    const float* __restrict__ emb,
    const float* __restrict__ Wih,
    const float* __restrict__ bih,
    const float* __restrict__ bhh)
{
    extern __shared__ __align__(16) float sm[];
    unsigned* BHI  = reinterpret_cast<unsigned*>(sm);
    unsigned* BLO  = reinterpret_cast<unsigned*>(sm + 12800);
    unsigned* AHI  = reinterpret_cast<unsigned*>(sm + 25600);
    unsigned* ALO  = reinterpret_cast<unsigned*>(sm + 29952);
    float*    bsum = sm + 34304;

    const int tid  = threadIdx.x;
    const int lane = tid & 31;
    const int wid  = tid >> 5;
    const int wm   = wid >> 3;
    const int ng   = wid & 7;
    const int ntb  = (ng == 0) ? 0 : (4 + 3 * (ng - 1));
    const int ncnt = (ng == 0) ? 4 : 3;

    const int r_ln = lane >> 2;
    const int c_ln = lane & 3;

    const int lrow  = (lane & 7) + ((lane >> 3) & 1) * 8;
    const int khalf = lane >> 4;
    int aoff[2];
#pragma unroll
    for (int f = 0; f < 2; f++)
        aoff[f] = (wm * 32 + f * 16 + lrow) * 68 + khalf * 4;
    const unsigned ahi_b = smem_u32(AHI);
    const unsigned alo_b = smem_u32(ALO);

    // stage Wih as hi/lo bf16 frag planes (h-paired layout)
    for (int i = tid; i < 12800; i += 512) {
        const int nn = i >> 6;
        const int kp = i & 63;
        const int s  = kp >> 3;
        const int hh = (kp >> 2) & 1;
        const int cc = kp & 3;
        const int nt = nn >> 3;
        const int gg = nn & 7;
        const int dst = (((s * 25 + nt) * 32) + gg * 4 + cc) * 2 + hh;
        const float2 v = *reinterpret_cast<const float2*>(Wih + nn * 128 + 2 * kp);
        __nv_bfloat16 h0, l0, h1, l1;
        bf16_split(v.x, h0, l0);
        bf16_split(v.y, h1, l1);
        BHI[dst] = pack_bf2(h0, h1);
        BLO[dst] = pack_bf2(l0, l1);
    }
    if (tid < 200) bsum[tid] = bih[tid] + bhh[tid];

    const int grow = tid >> 3;   // gather: row within tile (0..63)
    const int gsub = tid & 7;    // 16-float chunk within row

    int tok_next = tokens[blockIdx.x * 64 + grow];

    for (int tile = blockIdx.x; tile < 800; tile += 148) {
        const int row0 = tile * 64;
        const int tok  = tok_next;

        // ---- gather + convert (direct LDG, no staging) ----
        {
            const float4* src = reinterpret_cast<const float4*>(
                emb + (size_t)tok * 128 + gsub * 16);
            const float4 v0 = src[0], v1 = src[1], v2 = src[2], v3 = src[3];
            // prefetch next tile's token while the gather is in flight
            if (tile + 148 < 800) tok_next = tokens[(tile + 148) * 64 + grow];
            const float xsrc[16] = {v0.x, v0.y, v0.z, v0.w, v1.x, v1.y, v1.z, v1.w,
                                    v2.x, v2.y, v2.z, v2.w, v3.x, v3.y, v3.z, v3.w};
            unsigned hw[8], lw[8];
#pragma unroll
            for (int p = 0; p < 8; p++) {
                __nv_bfloat16 h0, l0, h1, l1;
                bf16_split(xsrc[2 * p],     h0, l0);
                bf16_split(xsrc[2 * p + 1], h1, l1);
                hw[p] = pack_bf2(h0, h1);
                lw[p] = pack_bf2(l0, l1);
            }
            const int wbase = grow * 68 + gsub * 8;
            *reinterpret_cast<uint4*>(&AHI[wbase]) =
                make_uint4(hw[0], hw[1], hw[2], hw[3]);
            *reinterpret_cast<uint4*>(&AHI[wbase + 4]) =
                make_uint4(hw[4], hw[5], hw[6], hw[7]);
            *reinterpret_cast<uint4*>(&ALO[wbase]) =
                make_uint4(lw[0], lw[1], lw[2], lw[3]);
            *reinterpret_cast<uint4*>(&ALO[wbase + 4]) =
                make_uint4(lw[4], lw[5], lw[6], lw[7]);
        }
        __syncthreads();

        // ---- MMA ----
        float acc[4][2][4];
#pragma unroll
        for (int nt = 0; nt < 4; nt++)
#pragma unroll
            for (int f = 0; f < 2; f++)
#pragma unroll
                for (int e = 0; e < 4; e++) acc[nt][f][e] = 0.f;

#pragma unroll
        for (int s = 0; s < 8; s++) {
            unsigned ah[2][4], al[2][4];
#pragma unroll
            for (int f = 0; f < 2; f++) {
                ldsm_x4(ah[f], ahi_b + (unsigned)(aoff[f] + s * 8) * 4u);
                ldsm_x4(al[f], alo_b + (unsigned)(aoff[f] + s * 8) * 4u);
            }
#pragma unroll
            for (int nt = 0; nt < 4; nt++) {
                if (nt < ncnt) {
                    const int bw = (((s * 25 + ntb + nt) * 32) + lane) * 2;
                    const unsigned long long bh =
                        *reinterpret_cast<const unsigned long long*>(&BHI[bw]);
                    const unsigned long long bl =
                        *reinterpret_cast<const unsigned long long*>(&BLO[bw]);
                    const unsigned bh0 = (unsigned)bh, bh1 = (unsigned)(bh >> 32);
                    const unsigned bl0 = (unsigned)bl, bl1 = (unsigned)(bl >> 32);
#pragma unroll
                    for (int f = 0; f < 2; f++) {
                        mma_bf16(acc[nt][f], ah[f], bh0, bh1);
                        mma_bf16(acc[nt][f], ah[f], bl0, bl1);
                        mma_bf16(acc[nt][f], al[f], bh0, bh1);
                    }
                }
            }
        }

        // ---- epilogue ----
#pragma unroll
        for (int nt = 0; nt < 4; nt++) {
            if (nt < ncnt) {
                const int col = (ntb + nt) * 8 + 2 * c_ln;
                const float bx = bsum[col];
                const float by = bsum[col + 1];
#pragma unroll
                for (int f = 0; f < 2; f++) {
                    const int row = row0 + wm * 32 + f * 16 + r_ln;
                    float2 o0, o1;
                    o0.x = acc[nt][f][0] + bx;
                    o0.y = acc[nt][f][1] + by;
                    o1.x = acc[nt][f][2] + bx;
                    o1.y = acc[nt][f][3] + by;
                    *reinterpret_cast<float2*>(
                        &g_xproj[(size_t)row * 200 + col]) = o0;
                    *reinterpret_cast<float2*>(
                        &g_xproj[(size_t)(row + 8) * 200 + col]) = o1;
                }
            }
        }
        __syncthreads();
    }
}

// ---------------------------------------------------------------------------
// K2: LSTM recurrence (R5 cadence; loaders moved OFF the cell warps).
// 128 CTAs x 512 threads, 2 groups of 256; group g owns batch b = blk*2+g.
// Rotated role index v (g=1 -> (n+64)&255):
//   v < 200        : gate threads (dot)
//   v < 50         : also cell update + g_hs store  (no loading work!)
//   v in [200,250) : cp.async loaders for the 8-deep x_proj ring (idle warps)
// ---------------------------------------------------------------------------
#define S_ 8

__global__ __launch_bounds__(512, 1) void k2_lstm(const float* __restrict__ Whh)
{
    __shared__ __align__(16) float h_s[2][52];
    __shared__ float gates_s[2][200];
    __shared__ __align__(16) float xs[2][S_][200];

    const int tid = threadIdx.x;
    const int g   = tid >> 8;
    const int n   = tid & 255;
    const int v   = g ? ((n + 64) & 255) : n;   // rotated role index
    const int b   = blockIdx.x * 2 + g;

    const bool gate   = (v < 200);
    const bool loader = (v >= 200 && v < 250);
    const int  lj     = v - 200;

    unsigned long long w2[25];
    if (gate) {
        const float2* wr = reinterpret_cast<const float2*>(Whh + v * 50);
#pragma unroll
        for (int q = 0; q < 25; q++)
            w2[q] = *reinterpret_cast<const unsigned long long*>(&wr[q]);
    }
    if (v < 52) h_s[g][v] = 0.f;

    if (loader) {
#pragma unroll
        for (int s = 0; s < S_ - 1; s++) {
            cp16(smem_u32(&xs[g][s][lj * 4]),
                 g_xproj + ((size_t)(s * B_ + b) * 200) + lj * 4);
            asm volatile("cp.async.commit_group;");
        }
        asm volatile("cp.async.wait_group %0;" :: "n"(S_ - 3));
    }
    __syncthreads();

    float c = 0.f;

    for (int t = 0; t < T_; t++) {
        const int slot = t & (S_ - 1);

        if (loader) {
            const int ts = t + S_ - 1;
            if (ts < T_)
                cp16(smem_u32(&xs[g][ts & (S_ - 1)][lj * 4]),
                     g_xproj + ((size_t)(ts * B_ + b) * 200) + lj * 4);
            asm volatile("cp.async.commit_group;");
        }

        if (gate) {
            const float xp = xs[g][slot][v];
            const unsigned long long* h2 =
                reinterpret_cast<const unsigned long long*>(h_s[g]);
            unsigned long long a0 = 0ull, a1 = 0ull, a2 = 0ull, a3 = 0ull;
#pragma unroll
            for (int q = 0; q < 24; q += 4) {
                a0 = fma2(h2[q],     w2[q],     a0);
                a1 = fma2(h2[q + 1], w2[q + 1], a1);
                a2 = fma2(h2[q + 2], w2[q + 2], a2);
                a3 = fma2(h2[q + 3], w2[q + 3], a3);
            }
            a0 = fma2(h2[24], w2[24], a0);
            a0 = add2(a0, a1);
            a2 = add2(a2, a3);
            a0 = add2(a0, a2);
            const float2 s = u2f(a0);
            gates_s[g][v] = xp + s.x + s.y;
        } else if (loader) {
            asm volatile("cp.async.wait_group %0;" :: "n"(S_ - 3));
        }
        asm volatile("bar.sync %0, 256;" :: "r"(g + 1) : "memory");

        if (v < 50) {
            const float iv = gates_s[g][v];
            const float fv = gates_s[g][v + 50];
            const float gv = gates_s[g][v + 100];
            const float ov = gates_s[g][v + 150];
            const float si = sigm(iv);
            const float sf = sigm(fv);
            const float so = sigm(ov);
            const float tg = fmaf(2.f, sigm(2.f * gv), -1.f);
            c = fmaf(sf, c, si * tg);
            const float tc = fmaf(2.f, sigm(2.f * c), -1.f);
            const float hn = so * tc;
            h_s[g][v] = hn;
            g_hs[(size_t)(t * B_ + b) * 50 + v] = hn;
        }
        asm volatile("bar.sync %0, 256;" :: "r"(g + 1) : "memory");
    }
}

// ---------------------------------------------------------------------------
// K3 (v2): head with coalesced smem staging of the 256x50 h-block.
// ---------------------------------------------------------------------------
#define K3_SMEM_WORDS (12800 + 800 + 144 + 16 + 9)

__global__ __launch_bounds__(256) void k3_head(
    const float* __restrict__ W1, const float* __restrict__ b1,
    const float* __restrict__ W2, const float* __restrict__ b2,
    float* __restrict__ out)
{
    extern __shared__ __align__(16) float k3sm[];
    float* sh  = k3sm;             // 12800: 256 rows x 50
    float* sW1 = k3sm + 12800;     // 800
    float* sW2 = k3sm + 13600;     // 144
    float* sb1 = k3sm + 13744;     // 16
    float* sb2 = k3sm + 13760;     // 9

    const int tid = threadIdx.x;

    {
        const float4* src = reinterpret_cast<const float4*>(
            g_hs + (size_t)blockIdx.x * 12800);
        float4* dst = reinterpret_cast<float4*>(sh);
        for (int i = tid; i < 3200; i += 256) dst[i] = src[i];
    }
    for (int i = tid; i < 800; i += 256) sW1[i] = W1[i];
    if (tid < 144) sW2[tid] = W2[tid];
    if (tid < 16)  sb1[tid] = b1[tid];
    if (tid < 9)   sb2[tid] = b2[tid];
    __syncthreads();

    const int r = blockIdx.x * 256 + tid;
    const float* hrow = &sh[tid * 50];

    float z[16];
#pragma unroll
    for (int jj = 0; jj < 16; jj++) {
        float a = sb1[jj];
#pragma unroll
        for (int k = 0; k < 50; k++) a = fmaf(hrow[k], sW1[jj * 50 + k], a);
        z[jj] = fmaxf(a, 0.f);
    }
#pragma unroll
    for (int pp = 0; pp < 9; pp++) {
        float o = sb2[pp];
#pragma unroll
        for (int jj = 0; jj < 16; jj++) o = fmaf(z[jj], sW2[pp * 16 + jj], o);
        out[r * 9 + pp] = o;
    }
}

// ---------------------------------------------------------------------------
extern "C" void kernel_launch(void* const* d_in, const int* in_sizes, int n_in,
                              void* d_out, int out_size)
{
    const int*   tokens = (const int*)  d_in[0];
    const float* emb    = (const float*)d_in[1];
    const float* Wih    = (const float*)d_in[2];
    const float* Whh    = (const float*)d_in[3];
    const float* bih    = (const float*)d_in[4];
    const float* bhh    = (const float*)d_in[5];
    const float* W1     = (const float*)d_in[6];
    const float* b1     = (const float*)d_in[7];
    const float* W2     = (const float*)d_in[8];
    const float* b2     = (const float*)d_in[9];
    float* out = (float*)d_out;

    const int k1_smem = K1_SMEM_WORDS * 4;   // 138,016 B
    cudaFuncSetAttribute(k1_mma, cudaFuncAttributeMaxDynamicSharedMemorySize,
                         k1_smem);
    const int k3_smem = K3_SMEM_WORDS * 4;   // 55,076 B
    cudaFuncSetAttribute(k3_head, cudaFuncAttributeMaxDynamicSharedMemorySize,
                         k3_smem);

    k1_mma  <<<148, 512, k1_smem>>>(tokens, emb, Wih, bih, bhh);
    k2_lstm <<<B_ / 2, 512>>>(Whh);
    k3_head <<<M_ / 256, 256, k3_smem>>>(W1, b1, W2, b2, out);
}